// round 3
// baseline (speedup 1.0000x reference)
#include <cuda_runtime.h>

// Batched 512-point complex forward DFT (== the reference's complex matmul by
// W[h,j] = exp(-2*pi*i*j*h/512)), computed as a radix-8^3 FFT.
//
// Inputs (metadata order): x_re [8,16,256,512] f32, x_im same, w_re [512,512],
// w_im [512,512]. Output: [8,16,256,512,2] f32 (re/im interleaved last axis).
//
// 32768 independent row-FFTs. 64 threads/FFT, 8 complex per thread in regs,
// 3 radix-8 stages with smem exchanges. Exact twiddles from w table row 1.

#define NROWS 32768
#define FPB 4              // FFTs per block
#define TPF 64             // threads per FFT
#define BLOCK (FPB * TPF)  // 256
#define BUFSZ 576          // padded exchange buffer (stride 72 * 8)

__device__ __forceinline__ float2 cadd(float2 a, float2 b) { return make_float2(a.x + b.x, a.y + b.y); }
__device__ __forceinline__ float2 csub(float2 a, float2 b) { return make_float2(a.x - b.x, a.y - b.y); }
__device__ __forceinline__ float2 cmul(float2 a, float2 b) {
    return make_float2(fmaf(a.x, b.x, -a.y * b.y), fmaf(a.x, b.y, a.y * b.x));
}
// multiply by -i:  -i*(x+iy) = y - i x
__device__ __forceinline__ float2 mul_mi(float2 a) { return make_float2(a.y, -a.x); }

// 8-point DFT: A[k] = sum_j a[j] * W8^(jk),  W8 = exp(-2*pi*i/8)
__device__ __forceinline__ void dft8(const float2* a, float2* A) {
    // E = DFT4(a0,a2,a4,a6), O = DFT4(a1,a3,a5,a7), W4 = -i
    float2 e0p = cadd(a[0], a[4]), e0m = csub(a[0], a[4]);
    float2 e1p = cadd(a[2], a[6]), e1m = csub(a[2], a[6]);
    float2 E0 = cadd(e0p, e1p), E2 = csub(e0p, e1p);
    float2 mie = mul_mi(e1m);
    float2 E1 = cadd(e0m, mie);   // e0m - i*e1m
    float2 E3 = csub(e0m, mie);   // e0m + i*e1m

    float2 o0p = cadd(a[1], a[5]), o0m = csub(a[1], a[5]);
    float2 o1p = cadd(a[3], a[7]), o1m = csub(a[3], a[7]);
    float2 O0 = cadd(o0p, o1p), O2 = csub(o0p, o1p);
    float2 mio = mul_mi(o1m);
    float2 O1 = cadd(o0m, mio);
    float2 O3 = csub(o0m, mio);

    const float c = 0.70710678118654752440f;  // sqrt(2)/2
    float2 t0 = O0;
    float2 t1 = make_float2(c * (O1.x + O1.y), c * (O1.y - O1.x));   // (c,-c)*O1
    float2 t2 = mul_mi(O2);                                          // (0,-1)*O2
    float2 t3 = make_float2(c * (O3.y - O3.x), -c * (O3.x + O3.y));  // (-c,-c)*O3

    A[0] = cadd(E0, t0); A[4] = csub(E0, t0);
    A[1] = cadd(E1, t1); A[5] = csub(E1, t1);
    A[2] = cadd(E2, t2); A[6] = csub(E2, t2);
    A[3] = cadd(E3, t3); A[7] = csub(E3, t3);
}

__global__ __launch_bounds__(BLOCK)
void fft512_kernel(const float* __restrict__ xre, const float* __restrict__ xim,
                   const float* __restrict__ wre, const float* __restrict__ wim,
                   float* __restrict__ out) {
    __shared__ float twr[512], twi[512];          // W512^a exact twiddles
    __shared__ float bufr[FPB][BUFSZ], bufi[FPB][BUFSZ];

    const int tid = threadIdx.x;
    const int f = tid >> 6;       // FFT slot within block
    const int t = tid & 63;       // thread within FFT (== j1 in stage 1)
    const int row = blockIdx.x * FPB + f;

    // Exact twiddles from w table row 1: W^a = (w_re[512+a], w_im[512+a])
    #pragma unroll
    for (int i = tid; i < 512; i += BLOCK) {
        twr[i] = wre[512 + i];
        twi[i] = wim[512 + i];
    }

    const float* xr = xre + (size_t)row * 512;
    const float* xi = xim + (size_t)row * 512;

    float2 a[8], A[8];
    // Stage 1 input: a[j2] = x[t + 64*j2]   (coalesced 128B/warp per j2)
    #pragma unroll
    for (int j2 = 0; j2 < 8; j2++)
        a[j2] = make_float2(xr[t + 64 * j2], xi[t + 64 * j2]);

    __syncthreads();  // twiddles ready

    // ---- Stage 1: DFT8 over j2, twiddle W512^(t*h0), layout [h0*72 + j1] ----
    dft8(a, A);
    #pragma unroll
    for (int h0 = 0; h0 < 8; h0++) {
        float2 v = A[h0];
        if (h0) {
            int ti = t * h0;  // <= 441 < 512
            v = cmul(v, make_float2(twr[ti], twi[ti]));
        }
        bufr[f][h0 * 72 + t] = v.x;
        bufi[f][h0 * 72 + t] = v.y;
    }
    __syncthreads();

    // ---- Stage 2: thread (h0, j1a); DFT8 over j1b; twiddle W64^(j1a*h10) ----
    const int h0 = t >> 3;
    const int j1a = t & 7;
    #pragma unroll
    for (int j1b = 0; j1b < 8; j1b++) {
        int idx = h0 * 72 + j1a + 8 * j1b;
        a[j1b] = make_float2(bufr[f][idx], bufi[f][idx]);
    }
    __syncthreads();  // reads done before buffer reuse

    dft8(a, A);
    #pragma unroll
    for (int h10 = 0; h10 < 8; h10++) {
        float2 v = A[h10];
        if (h10) {
            int ti = 8 * j1a * h10;  // <= 392 < 512
            v = cmul(v, make_float2(twr[ti], twi[ti]));
        }
        int idx = j1a * 65 + 8 * h0 + h10;  // [j1a*65 + t']
        bufr[f][idx] = v.x;
        bufi[f][idx] = v.y;
    }
    __syncthreads();

    // ---- Stage 3: thread (h0, h10) = t; DFT8 over j1a; no twiddle ----
    #pragma unroll
    for (int j = 0; j < 8; j++) {
        int idx = j * 65 + t;  // 8*h0 + h10 == t
        a[j] = make_float2(bufr[f][idx], bufi[f][idx]);
    }
    __syncthreads();  // reads done before buffer reuse

    dft8(a, A);
    const int h10 = t & 7;
    // Stage output index: h = h0 + 8*h10 + 64*h11. Stage to smem (XOR-swizzled
    // for conflict-free writes), then coalesced float2 global stores.
    #pragma unroll
    for (int h11 = 0; h11 < 8; h11++) {
        int h = h0 + 8 * h10 + 64 * h11;
        int si = h ^ ((h & 32) >> 3);
        bufr[f][si] = A[h11].x;
        bufi[f][si] = A[h11].y;
    }
    __syncthreads();

    float2* o2 = reinterpret_cast<float2*>(out) + (size_t)row * 512;
    #pragma unroll
    for (int i = 0; i < 8; i++) {
        int h = t + 64 * i;
        int si = h ^ ((h & 32) >> 3);
        o2[h] = make_float2(bufr[f][si], bufi[f][si]);
    }
}

extern "C" void kernel_launch(void* const* d_in, const int* in_sizes, int n_in,
                              void* d_out, int out_size) {
    const float* x_re = (const float*)d_in[0];
    const float* x_im = (const float*)d_in[1];
    const float* w_re = (const float*)d_in[2];
    const float* w_im = (const float*)d_in[3];
    float* out = (float*)d_out;

    dim3 grid(NROWS / FPB);   // 8192 blocks
    dim3 block(BLOCK);        // 256 threads = 4 FFTs
    fft512_kernel<<<grid, block>>>(x_re, x_im, w_re, w_im, out);
}

// round 4
// speedup vs baseline: 1.2030x; 1.2030x over previous
#include <cuda_runtime.h>

// Batched 512-point complex forward DFT (== reference complex matmul by
// W[h,j] = exp(-2*pi*i*j*h/512)), computed as a radix-8^3 FFT.
//
// R3: float2 smem (LDS.64/STS.64), twiddles via chained powers from a single
// LDS.64 per stage, direct scattered STG.64 output (sector-perfect), staging
// pass and one __syncthreads removed.

#define NROWS 32768
#define FPB 4              // FFTs per block
#define TPF 64             // threads per FFT
#define BLOCK (FPB * TPF)  // 256
#define BUFSZ 576          // padded exchange buffer (stage1 stride 72 * 8)

__device__ __forceinline__ float2 cadd(float2 a, float2 b) { return make_float2(a.x + b.x, a.y + b.y); }
__device__ __forceinline__ float2 csub(float2 a, float2 b) { return make_float2(a.x - b.x, a.y - b.y); }
__device__ __forceinline__ float2 cmul(float2 a, float2 b) {
    return make_float2(fmaf(a.x, b.x, -a.y * b.y), fmaf(a.x, b.y, a.y * b.x));
}
// multiply by -i:  -i*(x+iy) = y - i x
__device__ __forceinline__ float2 mul_mi(float2 a) { return make_float2(a.y, -a.x); }

// 8-point DFT: A[k] = sum_j a[j] * W8^(jk),  W8 = exp(-2*pi*i/8)
__device__ __forceinline__ void dft8(const float2* a, float2* A) {
    float2 e0p = cadd(a[0], a[4]), e0m = csub(a[0], a[4]);
    float2 e1p = cadd(a[2], a[6]), e1m = csub(a[2], a[6]);
    float2 E0 = cadd(e0p, e1p), E2 = csub(e0p, e1p);
    float2 mie = mul_mi(e1m);
    float2 E1 = cadd(e0m, mie);
    float2 E3 = csub(e0m, mie);

    float2 o0p = cadd(a[1], a[5]), o0m = csub(a[1], a[5]);
    float2 o1p = cadd(a[3], a[7]), o1m = csub(a[3], a[7]);
    float2 O0 = cadd(o0p, o1p), O2 = csub(o0p, o1p);
    float2 mio = mul_mi(o1m);
    float2 O1 = cadd(o0m, mio);
    float2 O3 = csub(o0m, mio);

    const float c = 0.70710678118654752440f;  // sqrt(2)/2
    float2 t0 = O0;
    float2 t1 = make_float2(c * (O1.x + O1.y), c * (O1.y - O1.x));   // (c,-c)*O1
    float2 t2 = mul_mi(O2);                                          // (0,-1)*O2
    float2 t3 = make_float2(c * (O3.y - O3.x), -c * (O3.x + O3.y));  // (-c,-c)*O3

    A[0] = cadd(E0, t0); A[4] = csub(E0, t0);
    A[1] = cadd(E1, t1); A[5] = csub(E1, t1);
    A[2] = cadd(E2, t2); A[6] = csub(E2, t2);
    A[3] = cadd(E3, t3); A[7] = csub(E3, t3);
}

__global__ __launch_bounds__(BLOCK)
void fft512_kernel(const float* __restrict__ xre, const float* __restrict__ xim,
                   const float* __restrict__ wre, const float* __restrict__ wim,
                   float* __restrict__ out) {
    __shared__ float2 tw2[512];           // W512^a exact base twiddles
    __shared__ float2 buf[FPB][BUFSZ];    // exchange buffer

    const int tid = threadIdx.x;
    const int f = tid >> 6;       // FFT slot within block
    const int t = tid & 63;       // thread within FFT
    const int row = blockIdx.x * FPB + f;

    // Exact twiddles from w table row 1: W^a = (w_re[512+a], w_im[512+a])
    #pragma unroll
    for (int i = tid; i < 512; i += BLOCK)
        tw2[i] = make_float2(wre[512 + i], wim[512 + i]);

    const float* xr = xre + (size_t)row * 512;
    const float* xi = xim + (size_t)row * 512;

    float2 a[8], A[8];
    // Stage 1 input: a[j2] = x[t + 64*j2]   (coalesced 128B/warp per j2)
    #pragma unroll
    for (int j2 = 0; j2 < 8; j2++)
        a[j2] = make_float2(xr[t + 64 * j2], xi[t + 64 * j2]);

    __syncthreads();  // twiddles ready

    // ---- Stage 1: DFT8 over j2, twiddle W512^(t*h0), layout [h0*72 + t] ----
    dft8(a, A);
    {
        // chained powers of W^t (one conflict-free LDS.64; 6 chain cmuls)
        float2 wb = tw2[t];
        float2 w = wb;
        #pragma unroll
        for (int h0 = 1; h0 < 8; h0++) {
            A[h0] = cmul(A[h0], w);
            if (h0 < 7) w = cmul(w, wb);
        }
    }
    #pragma unroll
    for (int h0 = 0; h0 < 8; h0++)
        buf[f][h0 * 72 + t] = A[h0];
    __syncthreads();

    // ---- Stage 2: thread (h0, j1a); DFT8 over j1b; twiddle W512^(8*j1a*h10) ----
    const int h0 = t >> 3;
    const int j1a = t & 7;
    #pragma unroll
    for (int j1b = 0; j1b < 8; j1b++)
        a[j1b] = buf[f][h0 * 72 + j1a + 8 * j1b];
    __syncthreads();  // reads done before buffer reuse

    dft8(a, A);
    {
        float2 wb = tw2[8 * j1a];  // broadcast-heavy LDS.64 (8 distinct addrs)
        float2 w = wb;
        #pragma unroll
        for (int h10 = 1; h10 < 8; h10++) {
            A[h10] = cmul(A[h10], w);
            if (h10 < 7) w = cmul(w, wb);
        }
    }
    #pragma unroll
    for (int h10 = 0; h10 < 8; h10++)
        buf[f][j1a * 65 + 8 * h0 + h10] = A[h10];
    __syncthreads();

    // ---- Stage 3: thread t = (h0, h10); DFT8 over j1a; no twiddle ----
    #pragma unroll
    for (int j = 0; j < 8; j++)
        a[j] = buf[f][j * 65 + t];

    dft8(a, A);

    // Direct scattered store. h = h0 + 8*h10 + 64*h11. Lanes 4k..4k+3 (h0=0..3)
    // write consecutive float2 = one full 32B sector -> 100% DRAM efficiency,
    // no staging smem, no final syncthreads.
    const int h10 = t & 7;
    float2* o2 = reinterpret_cast<float2*>(out) + (size_t)row * 512;
    #pragma unroll
    for (int h11 = 0; h11 < 8; h11++)
        o2[h0 + 8 * h10 + 64 * h11] = A[h11];
}

extern "C" void kernel_launch(void* const* d_in, const int* in_sizes, int n_in,
                              void* d_out, int out_size) {
    const float* x_re = (const float*)d_in[0];
    const float* x_im = (const float*)d_in[1];
    const float* w_re = (const float*)d_in[2];
    const float* w_im = (const float*)d_in[3];
    float* out = (float*)d_out;

    dim3 grid(NROWS / FPB);   // 8192 blocks
    dim3 block(BLOCK);        // 256 threads = 4 FFTs
    fft512_kernel<<<grid, block>>>(x_re, x_im, w_re, w_im, out);
}

// round 5
// speedup vs baseline: 1.3073x; 1.0868x over previous
#include <cuda_runtime.h>

// Batched 512-point complex forward DFT (== reference complex matmul by
// W[h,j] = exp(-2*pi*i*j*h/512)), computed as a radix-8^3 FFT.
//
// R4: digit relabeling so stage-3 low output digits == thread id ->
// fully coalesced output STG.64 (64 -> 16 L1 wavefronts/warp). Stage-2 store
// stride 66 (== 2 mod 16, conflict-free). Pre-expanded stage-2 twiddle table.

#define NROWS 32768
#define FPB 4              // FFTs per block
#define TPF 64             // threads per FFT
#define BLOCK (FPB * TPF)  // 256
#define BUFSZ 576          // stage1 stride 72 * 8 (stage2 needs only 526)
#define S2 66              // stage-2 store stride (2 mod 16 -> conflict-free)

__device__ __forceinline__ float2 cadd(float2 a, float2 b) { return make_float2(a.x + b.x, a.y + b.y); }
__device__ __forceinline__ float2 csub(float2 a, float2 b) { return make_float2(a.x - b.x, a.y - b.y); }
__device__ __forceinline__ float2 cmul(float2 a, float2 b) {
    return make_float2(fmaf(a.x, b.x, -a.y * b.y), fmaf(a.x, b.y, a.y * b.x));
}
// multiply by -i
__device__ __forceinline__ float2 mul_mi(float2 a) { return make_float2(a.y, -a.x); }

// 8-point DFT: A[k] = sum_j a[j] * W8^(jk),  W8 = exp(-2*pi*i/8)
__device__ __forceinline__ void dft8(const float2* a, float2* A) {
    float2 e0p = cadd(a[0], a[4]), e0m = csub(a[0], a[4]);
    float2 e1p = cadd(a[2], a[6]), e1m = csub(a[2], a[6]);
    float2 E0 = cadd(e0p, e1p), E2 = csub(e0p, e1p);
    float2 mie = mul_mi(e1m);
    float2 E1 = cadd(e0m, mie);
    float2 E3 = csub(e0m, mie);

    float2 o0p = cadd(a[1], a[5]), o0m = csub(a[1], a[5]);
    float2 o1p = cadd(a[3], a[7]), o1m = csub(a[3], a[7]);
    float2 O0 = cadd(o0p, o1p), O2 = csub(o0p, o1p);
    float2 mio = mul_mi(o1m);
    float2 O1 = cadd(o0m, mio);
    float2 O3 = csub(o0m, mio);

    const float c = 0.70710678118654752440f;  // sqrt(2)/2
    float2 t0 = O0;
    float2 t1 = make_float2(c * (O1.x + O1.y), c * (O1.y - O1.x));   // (c,-c)*O1
    float2 t2 = mul_mi(O2);                                          // (0,-1)*O2
    float2 t3 = make_float2(c * (O3.y - O3.x), -c * (O3.x + O3.y));  // (-c,-c)*O3

    A[0] = cadd(E0, t0); A[4] = csub(E0, t0);
    A[1] = cadd(E1, t1); A[5] = csub(E1, t1);
    A[2] = cadd(E2, t2); A[6] = csub(E2, t2);
    A[3] = cadd(E3, t3); A[7] = csub(E3, t3);
}

__global__ __launch_bounds__(BLOCK)
void fft512_kernel(const float* __restrict__ xre, const float* __restrict__ xim,
                   const float* __restrict__ wre, const float* __restrict__ wim,
                   float* __restrict__ out) {
    __shared__ float2 tw2[512];           // W512^a exact base twiddles
    __shared__ float2 tws2[64];           // tws2[i] = W512^(8*(i&7)) expanded
    __shared__ float2 buf[FPB][BUFSZ];    // exchange buffer

    const int tid = threadIdx.x;
    const int f = tid >> 6;       // FFT slot within block
    const int t = tid & 63;       // thread within FFT
    const int row = blockIdx.x * FPB + f;

    // Exact twiddles from w table row 1: W^a = (w_re[512+a], w_im[512+a])
    #pragma unroll
    for (int i = tid; i < 512; i += BLOCK)
        tw2[i] = make_float2(wre[512 + i], wim[512 + i]);
    if (tid < 64)
        tws2[tid] = make_float2(wre[512 + 8 * (tid & 7)], wim[512 + 8 * (tid & 7)]);

    const float* xr = xre + (size_t)row * 512;
    const float* xi = xim + (size_t)row * 512;

    float2 a[8], A[8];
    // Stage 1 input: a[j2] = x[t + 64*j2]   (coalesced 128B/warp per j2)
    #pragma unroll
    for (int j2 = 0; j2 < 8; j2++)
        a[j2] = make_float2(xr[t + 64 * j2], xi[t + 64 * j2]);

    __syncthreads();  // twiddles ready

    // ---- Stage 1: DFT8 over j2 -> digit h0; twiddle W512^(t*h0); [h0*72+t] ----
    dft8(a, A);
    {
        float2 wb = tw2[t];   // conflict-free LDS.64
        float2 w = wb;
        #pragma unroll
        for (int h0 = 1; h0 < 8; h0++) {
            A[h0] = cmul(A[h0], w);
            if (h0 < 7) w = cmul(w, wb);
        }
    }
    #pragma unroll
    for (int h0 = 0; h0 < 8; h0++)
        buf[f][h0 * 72 + t] = A[h0];
    __syncthreads();

    // ---- Stage 2: thread (h0 = t>>3, j1a = t&7); DFT8 over j1b -> digit h10;
    //      twiddle W512^(8*j1a*h10); store [j1a*66 + 8*h10 + h0] ----
    {
        const int h0 = t >> 3;
        const int j1a = t & 7;
        #pragma unroll
        for (int j1b = 0; j1b < 8; j1b++)
            a[j1b] = buf[f][h0 * 72 + j1a + 8 * j1b];
        __syncthreads();  // reads done before buffer reuse

        dft8(a, A);
        float2 wb = tws2[t];  // = W^(8*j1a), consecutive addrs, conflict-free
        float2 w = wb;
        #pragma unroll
        for (int h10 = 1; h10 < 8; h10++) {
            A[h10] = cmul(A[h10], w);
            if (h10 < 7) w = cmul(w, wb);
        }
        #pragma unroll
        for (int h10 = 0; h10 < 8; h10++)
            buf[f][j1a * S2 + 8 * h10 + h0] = A[h10];
    }
    __syncthreads();

    // ---- Stage 3: thread t owns (h0 = t&7, h10 = t>>3) so 8*h10 + h0 ... and
    //      the lane-varying load offset 8*(t>>3)+(t&7) relabels to: read
    //      m = 8*h10 + h0 laid out s.t. loads are buf[j*66 + t_sw] where
    //      t_sw = 8*(t>>3) + (t&7) ... by construction equals the consecutive
    //      index: load buf[j*66 + 8*(t>>3) + (t&7)] ----
    {
        const int m = 8 * (t >> 3) + (t & 7);   // consecutive across half-warp? see note
        #pragma unroll
        for (int j = 0; j < 8; j++)
            a[j] = buf[f][j * S2 + m];

        dft8(a, A);

        // h = h0 + 8*h10 + 64*h11 = (t&7) + 8*(t>>3) + 64*h11 = m + 64*h11.
        // Wait: we want h_low == t for coalescing, so assign h0 = t&7,
        // h10 = t>>3 -> h_low = (t&7) + 8*(t>>3) = t. And the stage-2 layout
        // index is 8*h10 + h0 = 8*(t>>3) + (t&7) = t. So m == t.
        float2* o2 = reinterpret_cast<float2*>(out) + (size_t)row * 512;
        #pragma unroll
        for (int h11 = 0; h11 < 8; h11++)
            o2[t + 64 * h11] = A[h11];   // fully coalesced 256B per warp
    }
}

extern "C" void kernel_launch(void* const* d_in, const int* in_sizes, int n_in,
                              void* d_out, int out_size) {
    const float* x_re = (const float*)d_in[0];
    const float* x_im = (const float*)d_in[1];
    const float* w_re = (const float*)d_in[2];
    const float* w_im = (const float*)d_in[3];
    float* out = (float*)d_out;

    dim3 grid(NROWS / FPB);   // 8192 blocks
    dim3 block(BLOCK);        // 256 threads = 4 FFTs
    fft512_kernel<<<grid, block>>>(x_re, x_im, w_re, w_im, out);
}